// round 13
// baseline (speedup 1.0000x reference)
#include <cuda_runtime.h>
#include <math.h>

#define NN 8192
#define DD 1152
#define EE 262144

typedef unsigned int uint32;

// -------- scratch (allocation-free: static device globals) --------
__device__ float g_q[(size_t)NN * DD];
__device__ float g_k[(size_t)NN * DD];
__device__ float g_v[(size_t)NN * DD];
__device__ float g_o[(size_t)NN * DD];

// -------- tf32 mma helper --------
__device__ __forceinline__ void mma_tf32(float* d,
                                         uint32 a0, uint32 a1, uint32 a2, uint32 a3,
                                         uint32 b0, uint32 b1) {
    asm("mma.sync.aligned.m16n8k8.row.col.f32.tf32.tf32.f32 "
        "{%0,%1,%2,%3}, {%4,%5,%6,%7}, {%8,%9}, {%0,%1,%2,%3};"
        : "+f"(d[0]), "+f"(d[1]), "+f"(d[2]), "+f"(d[3])
        : "r"(a0), "r"(a1), "r"(a2), "r"(a3), "r"(b0), "r"(b1));
}

// -------- cp.async helpers --------
__device__ __forceinline__ void cp16(void* smem, const void* gmem) {
    uint32 s = (uint32)__cvta_generic_to_shared(smem);
    asm volatile("cp.async.cg.shared.global [%0], [%1], 16;" :: "r"(s), "l"(gmem));
}
__device__ __forceinline__ void cp_commit() { asm volatile("cp.async.commit_group;"); }
__device__ __forceinline__ void cp_wait0()  { asm volatile("cp.async.wait_group 0;" ::: "memory"); }
__device__ __forceinline__ void cp_wait1()  { asm volatile("cp.async.wait_group 1;" ::: "memory"); }

// ====================== rot kernel ======================
__global__ void rot_kernel(const float* __restrict__ ev,
                           const float* __restrict__ er,
                           float* __restrict__ rot)
{
    int e = blockIdx.x * 256 + threadIdx.x;
    if (e >= EE) return;
    float vx = ev[3*e+0], vy = ev[3*e+1], vz = ev[3*e+2];
    float dist = sqrtf(vx*vx + vy*vy + vz*vz);
    float nx0 = vx/dist, nx1 = vy/dist, nx2 = vz/dist;

    float r0 = er[3*e+0]-0.5f, r1 = er[3*e+1]-0.5f, r2 = er[3*e+2]-0.5f;
    float rn = sqrtf(r0*r0 + r1*r1 + r2*r2);
    float a0 = r0/rn, a1 = r1/rn, a2 = r2/rn;
    float b0 = -a1, b1 = a0, b2 = a2;
    float c0 = a0, c1 = -a2, c2 = a1;

    float da = fabsf(a0*nx0 + a1*nx1 + a2*nx2);
    float db = fabsf(b0*nx0 + b1*nx1 + b2*nx2);
    float dc = fabsf(c0*nx0 + c1*nx1 + c2*nx2);

    float e0 = a0, e1 = a1, e2c_ = a2, dcur = da;
    if (dcur > db) { e0 = b0; e1 = b1; e2c_ = b2; dcur = db; }
    if (dcur > dc) { e0 = c0; e1 = c1; e2c_ = c2; }

    float z0 = nx1*e2c_ - nx2*e1;
    float z1 = nx2*e0   - nx0*e2c_;
    float z2 = nx0*e1   - nx1*e0;
    float zn = sqrtf(z0*z0 + z1*z1 + z2*z2);
    z0 /= zn; z1 /= zn; z2 /= zn;
    float y0 = nx1*z2 - nx2*z1;
    float y1 = nx2*z0 - nx0*z2;
    float y2 = nx0*z1 - nx1*z0;
    float yn = sqrtf(y0*y0 + y1*y1 + y2*y2);
    y0 /= yn; y1 /= yn; y2 /= yn;

    float* R = rot + (size_t)e * 9;
    R[0] =  z0; R[1] =  z1; R[2] =  z2;
    R[3] = nx0; R[4] = nx1; R[5] = nx2;
    R[6] = -y0; R[7] = -y1; R[8] = -y2;
}

#define PL 132

// ====================== fused QKV linear (R10-proven) ======================
template<int L>
__global__ void __launch_bounds__(256) qkv_tf32(const float* __restrict__ x,
                                                const float* __restrict__ Wq,
                                                const float* __restrict__ Wk,
                                                const float* __restrict__ Wv,
                                                float* __restrict__ q,
                                                float* __restrict__ k,
                                                float* __restrict__ v)
{
    constexpr int d = 2*L + 1;
    constexpr int s = (L == 0) ? 0 : (L == 1 ? 128 : 512);
    constexpr int ntiles = (NN * d) / 64;
    constexpr int PX = 128*d + 4;
    constexpr int NMAX = 64/d + 2;
    constexpr int TC = NMAX*32*d;
    constexpr int CH = (TC + 255)/256;

    extern __shared__ float sm[];
    float* Xs = sm;
    float* Bs = sm + NMAX*PX;

    const int tid  = threadIdx.x;
    const int lane = tid & 31, wid = tid >> 5;
    const int gr   = lane >> 2, th = lane & 3;
    const int wr   = wid >> 1, wc = wid & 1;
    const int obase = blockIdx.y * 32;

    for (int i = tid; i < 3*32*32; i += 256) {
        int wi = i >> 10, rem = i & 1023;
        int o = rem >> 5, c4 = (rem & 31) * 4;
        const float* wp = (wi == 0) ? Wq : (wi == 1 ? Wk : Wv);
        cp16(&Bs[(wi*32 + o)*PL + c4], &wp[(obase + o)*128 + c4]);
    }
    cp_commit();

    const float scale = 0.08838834764831845f;

    float4 xr[CH];
    {
        const int n0 = (blockIdx.x * 64) / d;
        #pragma unroll
        for (int u = 0; u < CH; u++) {
            int i = tid + u*256;
            if (i < TC) {
                int node = i / (32*d);
                int j = (i - node*32*d) * 4;
                int nn = n0 + node; if (nn > NN-1) nn = NN-1;
                xr[u] = *(const float4*)&x[(size_t)nn*DD + s + j];
            }
        }
    }
    cp_wait0();

    for (int t = blockIdx.x; t < ntiles; t += gridDim.x) {
        const int r0 = t * 64;
        const int n0 = r0 / d;

        __syncthreads();
        #pragma unroll
        for (int u = 0; u < CH; u++) {
            int i = tid + u*256;
            if (i < TC) {
                int node = i / (32*d);
                int j = (i - node*32*d) * 4;
                *(float4*)&Xs[node*PX + j] = xr[u];
            }
        }
        __syncthreads();

        const int t2 = t + gridDim.x;
        if (t2 < ntiles) {
            const int n02 = (t2 * 64) / d;
            #pragma unroll
            for (int u = 0; u < CH; u++) {
                int i = tid + u*256;
                if (i < TC) {
                    int node = i / (32*d);
                    int j = (i - node*32*d) * 4;
                    int nn = n02 + node; if (nn > NN-1) nn = NN-1;
                    xr[u] = *(const float4*)&x[(size_t)nn*DD + s + j];
                }
            }
        }

        const int rowA0 = r0 + wr*16 + gr;
        const int rowA1 = rowA0 + 8;
        const int nA0 = rowA0 / d, mA0 = rowA0 - nA0*d;
        const int nA1 = rowA1 / d, mA1 = rowA1 - nA1*d;
        const float* X0 = Xs + (nA0 - n0)*PX + mA0 + th*d;
        const float* X1 = Xs + (nA1 - n0)*PX + mA1 + th*d;

        float acc[3][2][4];
        #pragma unroll
        for (int wi = 0; wi < 3; wi++)
            #pragma unroll
            for (int nt = 0; nt < 2; nt++)
                #pragma unroll
                for (int j = 0; j < 4; j++) acc[wi][nt][j] = 0.f;

        #pragma unroll 4
        for (int ks = 0; ks < 16; ks++) {
            const int co = ks * 8 * d;
            uint32 a0 = __float_as_uint(X0[co      ]);
            uint32 a1 = __float_as_uint(X1[co      ]);
            uint32 a2 = __float_as_uint(X0[co + 4*d]);
            uint32 a3 = __float_as_uint(X1[co + 4*d]);
            #pragma unroll
            for (int wi = 0; wi < 3; wi++)
                #pragma unroll
                for (int nt = 0; nt < 2; nt++) {
                    const float* Br = Bs + (wi*32 + wc*16 + nt*8 + gr)*PL + ks*8 + th;
                    uint32 b0 = __float_as_uint(Br[0]);
                    uint32 b1 = __float_as_uint(Br[4]);
                    mma_tf32(acc[wi][nt], a0, a1, a2, a3, b0, b1);
                }
        }

        #pragma unroll
        for (int wi = 0; wi < 3; wi++) {
            float* yp = (wi == 0) ? q : (wi == 1 ? k : v);
            #pragma unroll
            for (int r = 0; r < 2; r++) {
                int rg = r0 + wr*16 + gr + 8*r;
                int n = rg / d, m = rg - n * d;
                float* yb = yp + (size_t)n*DD + s + m;
                #pragma unroll
                for (int nt = 0; nt < 2; nt++) {
                    int o = obase + wc*16 + nt*8 + 2*th;
                    yb[(o  )*d] = acc[wi][nt][2*r  ] * scale;
                    yb[(o+1)*d] = acc[wi][nt][2*r+1] * scale;
                }
            }
        }
    }
}

// ====================== W_o linear (R10-proven) ======================
template<int L>
__global__ void __launch_bounds__(256) wo_tf32(const float* __restrict__ x,
                                               const float* __restrict__ W,
                                               float* __restrict__ y)
{
    constexpr int d = 2*L + 1;
    constexpr int s = (L == 0) ? 0 : (L == 1 ? 128 : 512);
    constexpr int ntiles = (NN * d) / 64;
    constexpr int PX = 128*d + 4;
    constexpr int NMAX = 64/d + 2;
    constexpr int TC = NMAX*32*d;
    constexpr int CH = (TC + 255)/256;

    extern __shared__ float sm[];
    float* Xs = sm;
    float* Bs = sm + NMAX*PX;

    const int tid  = threadIdx.x;
    const int lane = tid & 31, wid = tid >> 5;
    const int gr   = lane >> 2, th = lane & 3;
    const int wr   = wid >> 1, wc = wid & 1;
    const int warpRow = wr * 16;
    const int colBase = wc * 64;

    const float* Wl = W + L * 16384;
    for (int i = tid; i < 4096; i += 256) {
        int o = i >> 5, c4 = (i & 31) * 4;
        cp16(&Bs[o*PL + c4], &Wl[o*128 + c4]);
    }
    cp_commit();

    const float scale = 0.08838834764831845f;

    float4 xr[CH];
    {
        const int n0 = (blockIdx.x * 64) / d;
        #pragma unroll
        for (int u = 0; u < CH; u++) {
            int i = tid + u*256;
            if (i < TC) {
                int node = i / (32*d);
                int j = (i - node*32*d) * 4;
                int nn = n0 + node; if (nn > NN-1) nn = NN-1;
                xr[u] = *(const float4*)&x[(size_t)nn*DD + s + j];
            }
        }
    }
    cp_wait0();

    for (int t = blockIdx.x; t < ntiles; t += gridDim.x) {
        const int r0 = t * 64;
        const int n0 = r0 / d;

        __syncthreads();
        #pragma unroll
        for (int u = 0; u < CH; u++) {
            int i = tid + u*256;
            if (i < TC) {
                int node = i / (32*d);
                int j = (i - node*32*d) * 4;
                *(float4*)&Xs[node*PX + j] = xr[u];
            }
        }
        __syncthreads();

        const int t2 = t + gridDim.x;
        if (t2 < ntiles) {
            const int n02 = (t2 * 64) / d;
            #pragma unroll
            for (int u = 0; u < CH; u++) {
                int i = tid + u*256;
                if (i < TC) {
                    int node = i / (32*d);
                    int j = (i - node*32*d) * 4;
                    int nn = n02 + node; if (nn > NN-1) nn = NN-1;
                    xr[u] = *(const float4*)&x[(size_t)nn*DD + s + j];
                }
            }
        }

        const int rowA0 = r0 + warpRow + gr;
        const int rowA1 = rowA0 + 8;
        const int nA0 = rowA0 / d, mA0 = rowA0 - nA0*d;
        const int nA1 = rowA1 / d, mA1 = rowA1 - nA1*d;
        const float* X0 = Xs + (nA0 - n0)*PX + mA0 + th*d;
        const float* X1 = Xs + (nA1 - n0)*PX + mA1 + th*d;

        float acc[8][4];
        #pragma unroll
        for (int nt = 0; nt < 8; nt++)
            #pragma unroll
            for (int j = 0; j < 4; j++) acc[nt][j] = 0.f;

        #pragma unroll 4
        for (int ks = 0; ks < 16; ks++) {
            const int co = ks * 8 * d;
            uint32 a0 = __float_as_uint(X0[co      ]);
            uint32 a1 = __float_as_uint(X1[co      ]);
            uint32 a2 = __float_as_uint(X0[co + 4*d]);
            uint32 a3 = __float_as_uint(X1[co + 4*d]);
            #pragma unroll
            for (int nt = 0; nt < 8; nt++) {
                const float* Br = Bs + (colBase + nt*8 + gr) * PL + ks*8 + th;
                uint32 b0 = __float_as_uint(Br[0]);
                uint32 b1 = __float_as_uint(Br[4]);
                mma_tf32(acc[nt], a0, a1, a2, a3, b0, b1);
            }
        }

        #pragma unroll
        for (int r = 0; r < 2; r++) {
            int rg = r0 + warpRow + gr + 8*r;
            int n = rg / d, m = rg - n * d;
            float* yb = y + (size_t)n*DD + s + m;
            #pragma unroll
            for (int nt = 0; nt < 8; nt++) {
                int o = colBase + nt*8 + 2*th;
                yb[(o  )*d] = acc[nt][2*r  ] * scale;
                yb[(o+1)*d] = acc[nt][2*r+1] * scale;
            }
        }
    }
}

// ====================== flash attention (pipelined, race-fixed) ======================
#define PQ 148
#define PVP 152
#define PP 52
#define PVB (32*PVP)

__global__ void __launch_bounds__(128) attn_kernel(const float* __restrict__ q,
                                                   const float* __restrict__ k,
                                                   const float* __restrict__ v,
                                                   float* __restrict__ o)
{
    extern __shared__ float sm[];
    float* Qs = sm;               // [64][148]
    float* Ks = Qs + 64*PQ;       // [32][148]
    float* Vs = Ks + 32*PQ;       // [2][32][152]
    float* Ps = Vs + 2*PVB;       // [64][52]

    const int tid  = threadIdx.x;
    const int wid  = tid >> 5, lane = tid & 31;
    const int gr   = lane >> 2, th = lane & 3;
    const int b    = blockIdx.y >> 3, h = blockIdx.y & 7;
    const int q0   = blockIdx.x * 64;
    const size_t hoff  = (size_t)h * 144;
    const size_t bbase = (size_t)b * 512;
    const float qscale = 1.0f / 12.0f;

    // prologue: Q + V(0) via cp.async (one group), K(0) into registers
    for (int f = tid; f < 64*36; f += 128) {
        int row = f / 36, cs = (f % 36) * 4;
        cp16(&Qs[row*PQ + cs], &q[(bbase + q0 + row) * DD + hoff + cs]);
    }
    for (int f = tid; f < 32*36; f += 128) {
        int row = f / 36, cs = (f % 36) * 4;
        cp16(&Vs[row*PVP + cs], &v[(bbase + row) * (size_t)DD + hoff + cs]);
    }
    cp_commit();

    float4 kreg[9];
    #pragma unroll
    for (int u = 0; u < 9; u++) {
        int f = tid + u*128;
        int row = f / 36, cs = (f % 36) * 4;
        kreg[u] = *(const float4*)&k[(bbase + row) * (size_t)DD + hoff + cs];
    }
    cp_wait0();

    float m_i[2] = {-1e30f, -1e30f};
    float l_i[2] = {0.f, 0.f};
    float oac[18][4];
    #pragma unroll
    for (int nt = 0; nt < 18; nt++)
        #pragma unroll
        for (int j = 0; j < 4; j++) oac[nt][j] = 0.f;

    const int warpRow = 16 * wid;

    for (int t = 0; t < 16; t++) {
        const int buf = t & 1;
        __syncthreads();   // prior iter's Ks/Vs readers done

        // publish K(t) from registers
        #pragma unroll
        for (int u = 0; u < 9; u++) {
            int f = tid + u*128;
            int row = f / 36, cs = (f % 36) * 4;
            *(float4*)&Ks[row*PQ + cs] = kreg[u];
        }

        // prefetch K(t+1) regs + V(t+1) cp.async (hidden behind compute)
        if (t < 15) {
            const int ktn = (t + 1) * 32;
            #pragma unroll
            for (int u = 0; u < 9; u++) {
                int f = tid + u*128;
                int row = f / 36, cs = (f % 36) * 4;
                kreg[u] = *(const float4*)&k[(bbase + ktn + row) * (size_t)DD + hoff + cs];
            }
            for (int f = tid; f < 32*36; f += 128) {
                int row = f / 36, cs = (f % 36) * 4;
                cp16(&Vs[(buf^1)*PVB + row*PVP + cs],
                     &v[(bbase + ktn + row) * (size_t)DD + hoff + cs]);
            }
            cp_commit();
            cp_wait1();    // V(t) complete; V(t+1) may stay in flight
        } else {
            cp_wait0();    // final iter: V(15) MUST be complete (race fix)
        }
        __syncthreads();   // Ks + V(t) visible to all warps

        float s_[4][4];
        #pragma unroll
        for (int nt = 0; nt < 4; nt++)
            #pragma unroll
            for (int j = 0; j < 4; j++) s_[nt][j] = 0.f;

        #pragma unroll 3
        for (int ks = 0; ks < 18; ks++) {
            int k0 = ks * 8;
            const float* Qr = Qs + k0 + th;
            uint32 a0 = __float_as_uint(Qr[(warpRow + gr    ) * PQ    ]);
            uint32 a1 = __float_as_uint(Qr[(warpRow + gr + 8) * PQ    ]);
            uint32 a2 = __float_as_uint(Qr[(warpRow + gr    ) * PQ + 4]);
            uint32 a3 = __float_as_uint(Qr[(warpRow + gr + 8) * PQ + 4]);
            #pragma unroll
            for (int nt = 0; nt < 4; nt++) {
                const float* Kr = Ks + (nt*8 + gr) * PQ + k0 + th;
                uint32 b0 = __float_as_uint(Kr[0]);
                uint32 b1 = __float_as_uint(Kr[4]);
                mma_tf32(s_[nt], a0, a1, a2, a3, b0, b1);
            }
        }

        #pragma unroll
        for (int nt = 0; nt < 4; nt++)
            #pragma unroll
            for (int j = 0; j < 4; j++) s_[nt][j] *= qscale;

        #pragma unroll
        for (int r = 0; r < 2; r++) {
            float rm = -1e30f;
            #pragma unroll
            for (int nt = 0; nt < 4; nt++)
                rm = fmaxf(rm, fmaxf(s_[nt][2*r], s_[nt][2*r+1]));
            rm = fmaxf(rm, __shfl_xor_sync(0xffffffffu, rm, 1));
            rm = fmaxf(rm, __shfl_xor_sync(0xffffffffu, rm, 2));
            float newm = fmaxf(m_i[r], rm);
            float rs = 0.f;
            #pragma unroll
            for (int nt = 0; nt < 4; nt++) {
                float p0 = __expf(s_[nt][2*r  ] - newm);
                float p1 = __expf(s_[nt][2*r+1] - newm);
                s_[nt][2*r] = p0; s_[nt][2*r+1] = p1;
                rs += p0 + p1;
            }
            rs += __shfl_xor_sync(0xffffffffu, rs, 1);
            rs += __shfl_xor_sync(0xffffffffu, rs, 2);
            float corr = __expf(m_i[r] - newm);
            l_i[r] = l_i[r] * corr + rs;
            m_i[r] = newm;
            #pragma unroll
            for (int nt = 0; nt < 18; nt++) {
                oac[nt][2*r  ] *= corr;
                oac[nt][2*r+1] *= corr;
            }
        }

        #pragma unroll
        for (int nt = 0; nt < 4; nt++) {
            int col = nt*8 + 2*th;
            Ps[(warpRow + gr    ) * PP + col    ] = s_[nt][0];
            Ps[(warpRow + gr    ) * PP + col + 1] = s_[nt][1];
            Ps[(warpRow + gr + 8) * PP + col    ] = s_[nt][2];
            Ps[(warpRow + gr + 8) * PP + col + 1] = s_[nt][3];
        }
        __syncwarp();

        const float* Vbb = Vs + buf*PVB;
        #pragma unroll
        for (int ks = 0; ks < 4; ks++) {
            int k0 = ks * 8;
            const float* Pr = Ps + k0 + th;
            uint32 a0 = __float_as_uint(Pr[(warpRow + gr    ) * PP    ]);
            uint32 a1 = __float_as_uint(Pr[(warpRow + gr + 8) * PP    ]);
            uint32 a2 = __float_as_uint(Pr[(warpRow + gr    ) * PP + 4]);
            uint32 a3 = __float_as_uint(Pr[(warpRow + gr + 8) * PP + 4]);
            const float* Vb = Vbb + (k0 + th) * PVP + gr;
            #pragma unroll
            for (int nt = 0; nt < 18; nt++) {
                uint32 b0 = __float_as_uint(Vb[nt*8]);
                uint32 b1 = __float_as_uint(Vb[nt*8 + 4*PVP]);
                mma_tf32(oac[nt], a0, a1, a2, a3, b0, b1);
            }
        }
    }

    #pragma unroll
    for (int r = 0; r < 2; r++) {
        float inv = 1.0f / l_i[r];
        int row = q0 + warpRow + gr + 8*r;
        float* ob = o + (bbase + row) * (size_t)DD + hoff;
        #pragma unroll
        for (int nt = 0; nt < 18; nt++) {
            int col = nt*8 + 2*th;
            ob[col    ] = oac[nt][2*r  ] * inv;
            ob[col + 1] = oac[nt][2*r+1] * inv;
        }
    }
}

// ====================== epilogue (R10-proven) ======================
__global__ void __launch_bounds__(256) epilogue_kernel(const float* __restrict__ x,
                                                       const float* __restrict__ attn,
                                                       const float* __restrict__ gamma,
                                                       const float* __restrict__ beta,
                                                       float* __restrict__ out)
{
    const int n = blockIdx.x;
    const int tid = threadIdx.x;
    const size_t base = (size_t)n * DD;

    __shared__ float red[8];
    __shared__ float mu_s, rv_s;

    float val = 0.f;
    if (tid < 128) val = x[base + tid] + attn[base + tid];
    float s1 = val, s2 = val * val;
    #pragma unroll
    for (int off = 16; off; off >>= 1) {
        s1 += __shfl_xor_sync(0xffffffffu, s1, off);
        s2 += __shfl_xor_sync(0xffffffffu, s2, off);
    }
    if (tid < 128 && (tid & 31) == 0) { red[(tid>>5)*2] = s1; red[(tid>>5)*2+1] = s2; }
    __syncthreads();
    if (tid == 0) {
        float t1 = red[0] + red[2] + red[4] + red[6];
        float t2 = red[1] + red[3] + red[5] + red[7];
        float mu = t1 * (1.f/128.f);
        float var = t2 * (1.f/128.f) - mu*mu;
        mu_s = mu;
        rv_s = rsqrtf(var + 1e-5f);
    }
    __syncthreads();
    const float mu = mu_s, rv = rv_s;

    for (int i = tid; i < DD; i += 256) {
        float vv = x[base + i] + attn[base + i];
        if (i < 128) {
            float z = (vv - mu) * rv * gamma[i] + beta[i];
            vv = z / (1.f + __expf(-z));
        }
        out[base + i] = vv;
    }
}

// ====================== launch ======================
extern "C" void kernel_launch(void* const* d_in, const int* in_sizes, int n_in,
                              void* d_out, int out_size)
{
    const float* x     = (const float*)d_in[0];
    const float* ev    = (const float*)d_in[1];
    const float* er    = (const float*)d_in[2];
    const float* Wq    = (const float*)d_in[3];
    const float* Wk    = (const float*)d_in[4];
    const float* Wv    = (const float*)d_in[5];
    const float* Wo    = (const float*)d_in[6];
    const float* gamma = (const float*)d_in[7];
    const float* beta  = (const float*)d_in[8];
    float* out  = (float*)d_out;
    float* rotp = out + (size_t)NN * DD;

    float *qp, *kp, *vp, *op;
    cudaGetSymbolAddress((void**)&qp, g_q);
    cudaGetSymbolAddress((void**)&kp, g_k);
    cudaGetSymbolAddress((void**)&vp, g_v);
    cudaGetSymbolAddress((void**)&op, g_o);

    const int SMF0 = (66*132 + 96*PL) * 4;   // 85536
    const int SMF1 = (23*388 + 96*PL) * 4;   // 86384
    const int SMF2 = (14*644 + 96*PL) * 4;   // 86752
    const int SMW0 = (66*132 + 128*PL) * 4;  // 102432
    const int SMW1 = (23*388 + 128*PL) * 4;  // 103280
    const int SMW2 = (14*644 + 128*PL) * 4;  // 103648
    const int SMA  = (64*PQ + 32*PQ + 2*32*PVP + 64*PP) * 4;  // 109056

    cudaFuncSetAttribute((const void*)qkv_tf32<0>, cudaFuncAttributeMaxDynamicSharedMemorySize, SMF0);
    cudaFuncSetAttribute((const void*)qkv_tf32<1>, cudaFuncAttributeMaxDynamicSharedMemorySize, SMF1);
    cudaFuncSetAttribute((const void*)qkv_tf32<2>, cudaFuncAttributeMaxDynamicSharedMemorySize, SMF2);
    cudaFuncSetAttribute((const void*)wo_tf32<0>,  cudaFuncAttributeMaxDynamicSharedMemorySize, SMW0);
    cudaFuncSetAttribute((const void*)wo_tf32<1>,  cudaFuncAttributeMaxDynamicSharedMemorySize, SMW1);
    cudaFuncSetAttribute((const void*)wo_tf32<2>,  cudaFuncAttributeMaxDynamicSharedMemorySize, SMW2);
    cudaFuncSetAttribute((const void*)attn_kernel, cudaFuncAttributeMaxDynamicSharedMemorySize, SMA);

    rot_kernel<<<EE/256, 256>>>(ev, er, rotp);

    qkv_tf32<0><<<dim3(32, 4), 256, SMF0>>>(x, Wq,         Wk,         Wv,         qp, kp, vp);
    qkv_tf32<1><<<dim3(96, 4), 256, SMF1>>>(x, Wq + 16384, Wk + 16384, Wv + 16384, qp, kp, vp);
    qkv_tf32<2><<<dim3(80, 4), 256, SMF2>>>(x, Wq + 32768, Wk + 32768, Wv + 32768, qp, kp, vp);

    attn_kernel<<<dim3(8, 128), 128, SMA>>>(qp, kp, vp, op);

    wo_tf32<0><<<128, 256, SMW0>>>(op, Wo, kp);
    wo_tf32<1><<<384, 256, SMW1>>>(op, Wo, kp);
    wo_tf32<2><<<320, 256, SMW2>>>(op, Wo, kp);

    epilogue_kernel<<<NN, 256>>>(x, kp, gamma, beta, out);
}

// round 15
// speedup vs baseline: 1.0931x; 1.0931x over previous
#include <cuda_runtime.h>
#include <math.h>

#define NN 8192
#define DD 1152
#define EE 262144

typedef unsigned int uint32;

// -------- scratch (allocation-free: static device globals) --------
__device__ float g_q[(size_t)NN * DD];
__device__ float g_k[(size_t)NN * DD];
__device__ float g_v[(size_t)NN * DD];
__device__ float g_o[(size_t)NN * DD];
__device__ float g_wp[4 * 3 * 16384];   // pair-packed weights [w][l][o][128]

// -------- tf32 mma helper --------
__device__ __forceinline__ void mma_tf32(float* d,
                                         uint32 a0, uint32 a1, uint32 a2, uint32 a3,
                                         uint32 b0, uint32 b1) {
    asm("mma.sync.aligned.m16n8k8.row.col.f32.tf32.tf32.f32 "
        "{%0,%1,%2,%3}, {%4,%5,%6,%7}, {%8,%9}, {%0,%1,%2,%3};"
        : "+f"(d[0]), "+f"(d[1]), "+f"(d[2]), "+f"(d[3])
        : "r"(a0), "r"(a1), "r"(a2), "r"(a3), "r"(b0), "r"(b1));
}

// -------- cp.async helpers --------
__device__ __forceinline__ void cp16(void* smem, const void* gmem) {
    uint32 s = (uint32)__cvta_generic_to_shared(smem);
    asm volatile("cp.async.cg.shared.global [%0], [%1], 16;" :: "r"(s), "l"(gmem));
}
__device__ __forceinline__ void cp_commit() { asm volatile("cp.async.commit_group;"); }
__device__ __forceinline__ void cp_wait0()  { asm volatile("cp.async.wait_group 0;"); }

// ====================== weight pack kernel ======================
// dst c = ks*8 + th*2 + e  <-  src k = ks*8 + th + 4e   (ks in [0,16))
__global__ void pack_w_kernel(const float* __restrict__ Wq,
                              const float* __restrict__ Wk,
                              const float* __restrict__ Wv,
                              const float* __restrict__ Wo,
                              float* __restrict__ wp)
{
    int idx = blockIdx.x * 256 + threadIdx.x;
    if (idx >= 4 * 49152) return;
    int w = idx / 49152, rem = idx % 49152;
    int oc = rem >> 7, c = rem & 127;     // oc = l*128+o combined row index
    int ks = c >> 3, r = c & 7;
    int th = r >> 1, e = r & 1;
    int src_k = ks*8 + th + 4*e;
    const float* W = (w == 0) ? Wq : (w == 1) ? Wk : (w == 2) ? Wv : Wo;
    wp[idx] = W[oc*128 + src_k];
}

// ====================== rot kernel ======================
__global__ void rot_kernel(const float* __restrict__ ev,
                           const float* __restrict__ er,
                           float* __restrict__ rot)
{
    int e = blockIdx.x * 256 + threadIdx.x;
    if (e >= EE) return;
    float vx = ev[3*e+0], vy = ev[3*e+1], vz = ev[3*e+2];
    float dist = sqrtf(vx*vx + vy*vy + vz*vz);
    float nx0 = vx/dist, nx1 = vy/dist, nx2 = vz/dist;

    float r0 = er[3*e+0]-0.5f, r1 = er[3*e+1]-0.5f, r2 = er[3*e+2]-0.5f;
    float rn = sqrtf(r0*r0 + r1*r1 + r2*r2);
    float a0 = r0/rn, a1 = r1/rn, a2 = r2/rn;
    float b0 = -a1, b1 = a0, b2 = a2;
    float c0 = a0, c1 = -a2, c2 = a1;

    float da = fabsf(a0*nx0 + a1*nx1 + a2*nx2);
    float db = fabsf(b0*nx0 + b1*nx1 + b2*nx2);
    float dc = fabsf(c0*nx0 + c1*nx1 + c2*nx2);

    float e0 = a0, e1 = a1, e2c_ = a2, dcur = da;
    if (dcur > db) { e0 = b0; e1 = b1; e2c_ = b2; dcur = db; }
    if (dcur > dc) { e0 = c0; e1 = c1; e2c_ = c2; }

    float z0 = nx1*e2c_ - nx2*e1;
    float z1 = nx2*e0   - nx0*e2c_;
    float z2 = nx0*e1   - nx1*e0;
    float zn = sqrtf(z0*z0 + z1*z1 + z2*z2);
    z0 /= zn; z1 /= zn; z2 /= zn;
    float y0 = nx1*z2 - nx2*z1;
    float y1 = nx2*z0 - nx0*z2;
    float y2 = nx0*z1 - nx1*z0;
    float yn = sqrtf(y0*y0 + y1*y1 + y2*y2);
    y0 /= yn; y1 /= yn; y2 /= yn;

    float* R = rot + (size_t)e * 9;
    R[0] =  z0; R[1] =  z1; R[2] =  z2;
    R[3] = nx0; R[4] = nx1; R[5] = nx2;
    R[6] = -y0; R[7] = -y1; R[8] = -y2;
}

#define PB 136   // packed-W smem pitch (==8 words mod 32 -> phase-exact LDS.64)

// ====================== fused QKV linear (packed-W LDS.64 B-frags) ======================
template<int L>
__global__ void __launch_bounds__(256) qkv_tf32(const float* __restrict__ x,
                                                const float* __restrict__ Wqp,
                                                const float* __restrict__ Wkp,
                                                const float* __restrict__ Wvp,
                                                float* __restrict__ q,
                                                float* __restrict__ k,
                                                float* __restrict__ v)
{
    constexpr int d = 2*L + 1;
    constexpr int s = (L == 0) ? 0 : (L == 1 ? 128 : 512);
    constexpr int ntiles = (NN * d) / 64;
    constexpr int PX = 128*d + 4;
    constexpr int NMAX = 64/d + 2;
    constexpr int TC = NMAX*32*d;
    constexpr int CH = (TC + 255)/256;

    extern __shared__ float sm[];
    float* Xs = sm;
    float* Bs = sm + NMAX*PX;       // [3][32][PB]

    const int tid  = threadIdx.x;
    const int lane = tid & 31, wid = tid >> 5;
    const int gr   = lane >> 2, th = lane & 3;
    const int wr   = wid >> 1, wc = wid & 1;
    const int obase = blockIdx.y * 32;

    for (int i = tid; i < 3*32*32; i += 256) {
        int wi = i >> 10, rem = i & 1023;
        int o = rem >> 5, c4 = (rem & 31) * 4;
        const float* wp = (wi == 0) ? Wqp : (wi == 1 ? Wkp : Wvp);
        cp16(&Bs[(wi*32 + o)*PB + c4], &wp[(obase + o)*128 + c4]);
    }
    cp_commit();

    const float scale = 0.08838834764831845f;

    float4 xr[CH];
    {
        const int n0 = (blockIdx.x * 64) / d;
        #pragma unroll
        for (int u = 0; u < CH; u++) {
            int i = tid + u*256;
            if (i < TC) {
                int node = i / (32*d);
                int j = (i - node*32*d) * 4;
                int nn = n0 + node; if (nn > NN-1) nn = NN-1;
                xr[u] = *(const float4*)&x[(size_t)nn*DD + s + j];
            }
        }
    }
    cp_wait0();

    for (int t = blockIdx.x; t < ntiles; t += gridDim.x) {
        const int r0 = t * 64;
        const int n0 = r0 / d;

        __syncthreads();
        #pragma unroll
        for (int u = 0; u < CH; u++) {
            int i = tid + u*256;
            if (i < TC) {
                int node = i / (32*d);
                int j = (i - node*32*d) * 4;
                *(float4*)&Xs[node*PX + j] = xr[u];
            }
        }
        __syncthreads();

        const int t2 = t + gridDim.x;
        if (t2 < ntiles) {
            const int n02 = (t2 * 64) / d;
            #pragma unroll
            for (int u = 0; u < CH; u++) {
                int i = tid + u*256;
                if (i < TC) {
                    int node = i / (32*d);
                    int j = (i - node*32*d) * 4;
                    int nn = n02 + node; if (nn > NN-1) nn = NN-1;
                    xr[u] = *(const float4*)&x[(size_t)nn*DD + s + j];
                }
            }
        }

        const int rowA0 = r0 + wr*16 + gr;
        const int rowA1 = rowA0 + 8;
        const int nA0 = rowA0 / d, mA0 = rowA0 - nA0*d;
        const int nA1 = rowA1 / d, mA1 = rowA1 - nA1*d;
        const float* X0 = Xs + (nA0 - n0)*PX + mA0 + th*d;
        const float* X1 = Xs + (nA1 - n0)*PX + mA1 + th*d;

        float acc[3][2][4];
        #pragma unroll
        for (int wi = 0; wi < 3; wi++)
            #pragma unroll
            for (int nt = 0; nt < 2; nt++)
                #pragma unroll
                for (int j = 0; j < 4; j++) acc[wi][nt][j] = 0.f;

        #pragma unroll 4
        for (int ks = 0; ks < 16; ks++) {
            const int co = ks * 8 * d;
            uint32 a0 = __float_as_uint(X0[co      ]);
            uint32 a1 = __float_as_uint(X1[co      ]);
            uint32 a2 = __float_as_uint(X0[co + 4*d]);
            uint32 a3 = __float_as_uint(X1[co + 4*d]);
            #pragma unroll
            for (int wi = 0; wi < 3; wi++)
                #pragma unroll
                for (int nt = 0; nt < 2; nt++) {
                    float2 bp = *(const float2*)&Bs[(wi*32 + wc*16 + nt*8 + gr)*PB + ks*8 + th*2];
                    mma_tf32(acc[wi][nt], a0, a1, a2, a3,
                             __float_as_uint(bp.x), __float_as_uint(bp.y));
                }
        }

        #pragma unroll
        for (int wi = 0; wi < 3; wi++) {
            float* yp = (wi == 0) ? q : (wi == 1 ? k : v);
            #pragma unroll
            for (int r = 0; r < 2; r++) {
                int rg = r0 + wr*16 + gr + 8*r;
                int n = rg / d, m = rg - n * d;
                float* yb = yp + (size_t)n*DD + s + m;
                #pragma unroll
                for (int nt = 0; nt < 2; nt++) {
                    int o = obase + wc*16 + nt*8 + 2*th;
                    yb[(o  )*d] = acc[wi][nt][2*r  ] * scale;
                    yb[(o+1)*d] = acc[wi][nt][2*r+1] * scale;
                }
            }
        }
    }
}

// ====================== W_o linear (packed-W LDS.64 B-frags) ======================
template<int L>
__global__ void __launch_bounds__(256) wo_tf32(const float* __restrict__ x,
                                               const float* __restrict__ Wp,
                                               float* __restrict__ y)
{
    constexpr int d = 2*L + 1;
    constexpr int s = (L == 0) ? 0 : (L == 1 ? 128 : 512);
    constexpr int ntiles = (NN * d) / 64;
    constexpr int PX = 128*d + 4;
    constexpr int NMAX = 64/d + 2;
    constexpr int TC = NMAX*32*d;
    constexpr int CH = (TC + 255)/256;

    extern __shared__ float sm[];
    float* Xs = sm;
    float* Bs = sm + NMAX*PX;       // [128][PB]

    const int tid  = threadIdx.x;
    const int lane = tid & 31, wid = tid >> 5;
    const int gr   = lane >> 2, th = lane & 3;
    const int wr   = wid >> 1, wc = wid & 1;
    const int warpRow = wr * 16;
    const int colBase = wc * 64;

    for (int i = tid; i < 4096; i += 256) {
        int o = i >> 5, c4 = (i & 31) * 4;
        cp16(&Bs[o*PB + c4], &Wp[o*128 + c4]);
    }
    cp_commit();

    const float scale = 0.08838834764831845f;

    float4 xr[CH];
    {
        const int n0 = (blockIdx.x * 64) / d;
        #pragma unroll
        for (int u = 0; u < CH; u++) {
            int i = tid + u*256;
            if (i < TC) {
                int node = i / (32*d);
                int j = (i - node*32*d) * 4;
                int nn = n0 + node; if (nn > NN-1) nn = NN-1;
                xr[u] = *(const float4*)&x[(size_t)nn*DD + s + j];
            }
        }
    }
    cp_wait0();

    for (int t = blockIdx.x; t < ntiles; t += gridDim.x) {
        const int r0 = t * 64;
        const int n0 = r0 / d;

        __syncthreads();
        #pragma unroll
        for (int u = 0; u < CH; u++) {
            int i = tid + u*256;
            if (i < TC) {
                int node = i / (32*d);
                int j = (i - node*32*d) * 4;
                *(float4*)&Xs[node*PX + j] = xr[u];
            }
        }
        __syncthreads();

        const int t2 = t + gridDim.x;
        if (t2 < ntiles) {
            const int n02 = (t2 * 64) / d;
            #pragma unroll
            for (int u = 0; u < CH; u++) {
                int i = tid + u*256;
                if (i < TC) {
                    int node = i / (32*d);
                    int j = (i - node*32*d) * 4;
                    int nn = n02 + node; if (nn > NN-1) nn = NN-1;
                    xr[u] = *(const float4*)&x[(size_t)nn*DD + s + j];
                }
            }
        }

        const int rowA0 = r0 + warpRow + gr;
        const int rowA1 = rowA0 + 8;
        const int nA0 = rowA0 / d, mA0 = rowA0 - nA0*d;
        const int nA1 = rowA1 / d, mA1 = rowA1 - nA1*d;
        const float* X0 = Xs + (nA0 - n0)*PX + mA0 + th*d;
        const float* X1 = Xs + (nA1 - n0)*PX + mA1 + th*d;

        float acc[8][4];
        #pragma unroll
        for (int nt = 0; nt < 8; nt++)
            #pragma unroll
            for (int j = 0; j < 4; j++) acc[nt][j] = 0.f;

        #pragma unroll 4
        for (int ks = 0; ks < 16; ks++) {
            const int co = ks * 8 * d;
            uint32 a0 = __float_as_uint(X0[co      ]);
            uint32 a1 = __float_as_uint(X1[co      ]);
            uint32 a2 = __float_as_uint(X0[co + 4*d]);
            uint32 a3 = __float_as_uint(X1[co + 4*d]);
            #pragma unroll
            for (int nt = 0; nt < 8; nt++) {
                float2 bp = *(const float2*)&Bs[(colBase + nt*8 + gr)*PB + ks*8 + th*2];
                mma_tf32(acc[nt], a0, a1, a2, a3,
                         __float_as_uint(bp.x), __float_as_uint(bp.y));
            }
        }

        #pragma unroll
        for (int r = 0; r < 2; r++) {
            int rg = r0 + warpRow + gr + 8*r;
            int n = rg / d, m = rg - n * d;
            float* yb = y + (size_t)n*DD + s + m;
            #pragma unroll
            for (int nt = 0; nt < 8; nt++) {
                int o = colBase + nt*8 + 2*th;
                yb[(o  )*d] = acc[nt][2*r  ] * scale;
                yb[(o+1)*d] = acc[nt][2*r+1] * scale;
            }
        }
    }
}

// ====================== flash attention (R10-proven, non-pipelined) ======================
#define PQ 148
#define PVP 152
#define PP 52

__global__ void __launch_bounds__(128) attn_kernel(const float* __restrict__ q,
                                                   const float* __restrict__ k,
                                                   const float* __restrict__ v,
                                                   float* __restrict__ o)
{
    extern __shared__ float sm[];
    float* Qs = sm;               // [64][148]
    float* Ks = Qs + 64*PQ;       // [32][148]
    float* Vs = Ks + 32*PQ;       // [32][152]
    float* Ps = Vs + 32*PVP;      // [64][52]

    const int tid  = threadIdx.x;
    const int wid  = tid >> 5, lane = tid & 31;
    const int gr   = lane >> 2, th = lane & 3;
    const int b    = blockIdx.y >> 3, h = blockIdx.y & 7;
    const int q0   = blockIdx.x * 64;
    const size_t hoff  = (size_t)h * 144;
    const size_t bbase = (size_t)b * 512;
    const float qscale = 1.0f / 12.0f;

    for (int f = tid; f < 64*36; f += 128) {
        int row = f / 36, cs = (f % 36) * 4;
        cp16(&Qs[row*PQ + cs], &q[(bbase + q0 + row) * DD + hoff + cs]);
    }
    cp_commit();

    float m_i[2] = {-1e30f, -1e30f};
    float l_i[2] = {0.f, 0.f};
    float oac[18][4];
    #pragma unroll
    for (int nt = 0; nt < 18; nt++)
        #pragma unroll
        for (int j = 0; j < 4; j++) oac[nt][j] = 0.f;

    const int warpRow = 16 * wid;

    for (int kt = 0; kt < 512; kt += 32) {
        __syncthreads();
        for (int f = tid; f < 32*36; f += 128) {
            int row = f / 36, cs = (f % 36) * 4;
            size_t g = (bbase + kt + row) * (size_t)DD + hoff + cs;
            cp16(&Ks[row*PQ  + cs], &k[g]);
            cp16(&Vs[row*PVP + cs], &v[g]);
        }
        cp_commit();
        cp_wait0();
        __syncthreads();

        float s_[4][4];
        #pragma unroll
        for (int nt = 0; nt < 4; nt++)
            #pragma unroll
            for (int j = 0; j < 4; j++) s_[nt][j] = 0.f;

        #pragma unroll 3
        for (int ks = 0; ks < 18; ks++) {
            int k0 = ks * 8;
            const float* Qr = Qs + k0 + th;
            uint32 a0 = __float_as_uint(Qr[(warpRow + gr    ) * PQ    ]);
            uint32 a1 = __float_as_uint(Qr[(warpRow + gr + 8) * PQ    ]);
            uint32 a2 = __float_as_uint(Qr[(warpRow + gr    ) * PQ + 4]);
            uint32 a3 = __float_as_uint(Qr[(warpRow + gr + 8) * PQ + 4]);
            #pragma unroll
            for (int nt = 0; nt < 4; nt++) {
                const float* Kr = Ks + (nt*8 + gr) * PQ + k0 + th;
                uint32 b0 = __float_as_uint(Kr[0]);
                uint32 b1 = __float_as_uint(Kr[4]);
                mma_tf32(s_[nt], a0, a1, a2, a3, b0, b1);
            }
        }

        #pragma unroll
        for (int nt = 0; nt < 4; nt++)
            #pragma unroll
            for (int j = 0; j < 4; j++) s_[nt][j] *= qscale;

        #pragma unroll
        for (int r = 0; r < 2; r++) {
            float rm = -1e30f;
            #pragma unroll
            for (int nt = 0; nt < 4; nt++)
                rm = fmaxf(rm, fmaxf(s_[nt][2*r], s_[nt][2*r+1]));
            rm = fmaxf(rm, __shfl_xor_sync(0xffffffffu, rm, 1));
            rm = fmaxf(rm, __shfl_xor_sync(0xffffffffu, rm, 2));
            float newm = fmaxf(m_i[r], rm);
            float rs = 0.f;
            #pragma unroll
            for (int nt = 0; nt < 4; nt++) {
                float p0 = __expf(s_[nt][2*r  ] - newm);
                float p1 = __expf(s_[nt][2*r+1] - newm);
                s_[nt][2*r] = p0; s_[nt][2*r+1] = p1;
                rs += p0 + p1;
            }
            rs += __shfl_xor_sync(0xffffffffu, rs, 1);
            rs += __shfl_xor_sync(0xffffffffu, rs, 2);
            float corr = __expf(m_i[r] - newm);
            l_i[r] = l_i[r] * corr + rs;
            m_i[r] = newm;
            #pragma unroll
            for (int nt = 0; nt < 18; nt++) {
                oac[nt][2*r  ] *= corr;
                oac[nt][2*r+1] *= corr;
            }
        }

        #pragma unroll
        for (int nt = 0; nt < 4; nt++) {
            int col = nt*8 + 2*th;
            Ps[(warpRow + gr    ) * PP + col    ] = s_[nt][0];
            Ps[(warpRow + gr    ) * PP + col + 1] = s_[nt][1];
            Ps[(warpRow + gr + 8) * PP + col    ] = s_[nt][2];
            Ps[(warpRow + gr + 8) * PP + col + 1] = s_[nt][3];
        }
        __syncwarp();

        #pragma unroll
        for (int ks = 0; ks < 4; ks++) {
            int k0 = ks * 8;
            const float* Pr = Ps + k0 + th;
            uint32 a0 = __float_as_uint(Pr[(warpRow + gr    ) * PP    ]);
            uint32 a1 = __float_as_uint(Pr[(warpRow + gr + 8) * PP    ]);
            uint32 a2 = __float_as_uint(Pr[(warpRow + gr    ) * PP + 4]);
            uint32 a3 = __float_as_uint(Pr[(warpRow + gr + 8) * PP + 4]);
            const float* Vb = Vs + (k0 + th) * PVP + gr;
            #pragma unroll
            for (int nt = 0; nt < 18; nt++) {
                uint32 b0 = __float_as_uint(Vb[nt*8]);
                uint32 b1 = __float_as_uint(Vb[nt*8 + 4*PVP]);
                mma_tf32(oac[nt], a0, a1, a2, a3, b0, b1);
            }
        }
    }

    #pragma unroll
    for (int r = 0; r < 2; r++) {
        float inv = 1.0f / l_i[r];
        int row = q0 + warpRow + gr + 8*r;
        float* ob = o + (bbase + row) * (size_t)DD + hoff;
        #pragma unroll
        for (int nt = 0; nt < 18; nt++) {
            int col = nt*8 + 2*th;
            ob[col    ] = oac[nt][2*r  ] * inv;
            ob[col + 1] = oac[nt][2*r+1] * inv;
        }
    }
}

// ====================== epilogue (R10-proven) ======================
__global__ void __launch_bounds__(256) epilogue_kernel(const float* __restrict__ x,
                                                       const float* __restrict__ attn,
                                                       const float* __restrict__ gamma,
                                                       const float* __restrict__ beta,
                                                       float* __restrict__ out)
{
    const int n = blockIdx.x;
    const int tid = threadIdx.x;
    const size_t base = (size_t)n * DD;

    __shared__ float red[8];
    __shared__ float mu_s, rv_s;

    float val = 0.f;
    if (tid < 128) val = x[base + tid] + attn[base + tid];
    float s1 = val, s2 = val * val;
    #pragma unroll
    for (int off = 16; off; off >>= 1) {
        s1 += __shfl_xor_sync(0xffffffffu, s1, off);
        s2 += __shfl_xor_sync(0xffffffffu, s2, off);
    }
    if (tid < 128 && (tid & 31) == 0) { red[(tid>>5)*2] = s1; red[(tid>>5)*2+1] = s2; }
    __syncthreads();
    if (tid == 0) {
        float t1 = red[0] + red[2] + red[4] + red[6];
        float t2 = red[1] + red[3] + red[5] + red[7];
        float mu = t1 * (1.f/128.f);
        float var = t2 * (1.f/128.f) - mu*mu;
        mu_s = mu;
        rv_s = rsqrtf(var + 1e-5f);
    }
    __syncthreads();
    const float mu = mu_s, rv = rv_s;

    for (int i = tid; i < DD; i += 256) {
        float vv = x[base + i] + attn[base + i];
        if (i < 128) {
            float z = (vv - mu) * rv * gamma[i] + beta[i];
            vv = z / (1.f + __expf(-z));
        }
        out[base + i] = vv;
    }
}

// ====================== launch ======================
extern "C" void kernel_launch(void* const* d_in, const int* in_sizes, int n_in,
                              void* d_out, int out_size)
{
    const float* x     = (const float*)d_in[0];
    const float* ev    = (const float*)d_in[1];
    const float* er    = (const float*)d_in[2];
    const float* Wq    = (const float*)d_in[3];
    const float* Wk    = (const float*)d_in[4];
    const float* Wv    = (const float*)d_in[5];
    const float* Wo    = (const float*)d_in[6];
    const float* gamma = (const float*)d_in[7];
    const float* beta  = (const float*)d_in[8];
    float* out  = (float*)d_out;
    float* rotp = out + (size_t)NN * DD;

    float *qp, *kp, *vp, *op, *wp;
    cudaGetSymbolAddress((void**)&qp, g_q);
    cudaGetSymbolAddress((void**)&kp, g_k);
    cudaGetSymbolAddress((void**)&vp, g_v);
    cudaGetSymbolAddress((void**)&op, g_o);
    cudaGetSymbolAddress((void**)&wp, g_wp);

    const int SMF0 = (66*132 + 96*PB) * 4;   // 87072
    const int SMF1 = (23*388 + 96*PB) * 4;   // 87920
    const int SMF2 = (14*644 + 96*PB) * 4;   // 88288
    const int SMW0 = (66*132 + 128*PB) * 4;  // 104480
    const int SMW1 = (23*388 + 128*PB) * 4;  // 105328
    const int SMW2 = (14*644 + 128*PB) * 4;  // 105696
    const int SMA  = (64*PQ + 32*PQ + 32*PVP + 64*PP) * 4;  // 89600

    cudaFuncSetAttribute((const void*)qkv_tf32<0>, cudaFuncAttributeMaxDynamicSharedMemorySize, SMF0);
    cudaFuncSetAttribute((const void*)qkv_tf32<1>, cudaFuncAttributeMaxDynamicSharedMemorySize, SMF1);
    cudaFuncSetAttribute((const void*)qkv_tf32<2>, cudaFuncAttributeMaxDynamicSharedMemorySize, SMF2);
    cudaFuncSetAttribute((const void*)wo_tf32<0>,  cudaFuncAttributeMaxDynamicSharedMemorySize, SMW0);
    cudaFuncSetAttribute((const void*)wo_tf32<1>,  cudaFuncAttributeMaxDynamicSharedMemorySize, SMW1);
    cudaFuncSetAttribute((const void*)wo_tf32<2>,  cudaFuncAttributeMaxDynamicSharedMemorySize, SMW2);
    cudaFuncSetAttribute((const void*)attn_kernel, cudaFuncAttributeMaxDynamicSharedMemorySize, SMA);

    pack_w_kernel<<<768, 256>>>(Wq, Wk, Wv, Wo, wp);
    rot_kernel<<<EE/256, 256>>>(ev, er, rotp);

    // packed weight bases: wp + w*49152 + L*16384
    qkv_tf32<0><<<dim3(32, 4), 256, SMF0>>>(x, wp,           wp + 49152,           wp + 2*49152,           qp, kp, vp);
    qkv_tf32<1><<<dim3(96, 4), 256, SMF1>>>(x, wp + 16384,   wp + 49152 + 16384,   wp + 2*49152 + 16384,   qp, kp, vp);
    qkv_tf32<2><<<dim3(80, 4), 256, SMF2>>>(x, wp + 32768,   wp + 49152 + 32768,   wp + 2*49152 + 32768,   qp, kp, vp);

    attn_kernel<<<dim3(8, 128), 128, SMA>>>(qp, kp, vp, op);

    wo_tf32<0><<<128, 256, SMW0>>>(op, wp + 3*49152,          kp);
    wo_tf32<1><<<384, 256, SMW1>>>(op, wp + 3*49152 + 16384,  kp);
    wo_tf32<2><<<320, 256, SMW2>>>(op, wp + 3*49152 + 32768,  kp);

    epilogue_kernel<<<NN, 256>>>(x, kp, gamma, beta, out);
}

// round 16
// speedup vs baseline: 1.1155x; 1.0205x over previous
#include <cuda_runtime.h>
#include <math.h>

#define NN 8192
#define DD 1152
#define EE 262144

typedef unsigned int uint32;

// -------- scratch (allocation-free: static device globals) --------
__device__ float g_q[(size_t)NN * DD];
__device__ float g_k[(size_t)NN * DD];
__device__ float g_v[(size_t)NN * DD];
__device__ float g_o[(size_t)NN * DD];
__device__ float g_wp[4 * 3 * 16384];   // pair-packed weights [w][l][o][128]

// -------- tf32 mma helper --------
__device__ __forceinline__ void mma_tf32(float* d,
                                         uint32 a0, uint32 a1, uint32 a2, uint32 a3,
                                         uint32 b0, uint32 b1) {
    asm("mma.sync.aligned.m16n8k8.row.col.f32.tf32.tf32.f32 "
        "{%0,%1,%2,%3}, {%4,%5,%6,%7}, {%8,%9}, {%0,%1,%2,%3};"
        : "+f"(d[0]), "+f"(d[1]), "+f"(d[2]), "+f"(d[3])
        : "r"(a0), "r"(a1), "r"(a2), "r"(a3), "r"(b0), "r"(b1));
}

// -------- cp.async helpers --------
__device__ __forceinline__ void cp16(void* smem, const void* gmem) {
    uint32 s = (uint32)__cvta_generic_to_shared(smem);
    asm volatile("cp.async.cg.shared.global [%0], [%1], 16;" :: "r"(s), "l"(gmem));
}
__device__ __forceinline__ void cp_commit() { asm volatile("cp.async.commit_group;"); }
__device__ __forceinline__ void cp_wait0()  { asm volatile("cp.async.wait_group 0;"); }

// ====================== weight pack kernel ======================
// dst c = ks*8 + th*2 + e  <-  src k = ks*8 + th + 4e   (ks in [0,16))
__global__ void pack_w_kernel(const float* __restrict__ Wq,
                              const float* __restrict__ Wk,
                              const float* __restrict__ Wv,
                              const float* __restrict__ Wo,
                              float* __restrict__ wp)
{
    int idx = blockIdx.x * 256 + threadIdx.x;
    if (idx >= 4 * 49152) return;
    int w = idx / 49152, rem = idx % 49152;
    int oc = rem >> 7, c = rem & 127;
    int ks = c >> 3, r = c & 7;
    int th = r >> 1, e = r & 1;
    int src_k = ks*8 + th + 4*e;
    const float* W = (w == 0) ? Wq : (w == 1) ? Wk : (w == 2) ? Wv : Wo;
    wp[idx] = W[oc*128 + src_k];
}

// ====================== rot kernel ======================
__global__ void rot_kernel(const float* __restrict__ ev,
                           const float* __restrict__ er,
                           float* __restrict__ rot)
{
    int e = blockIdx.x * 256 + threadIdx.x;
    if (e >= EE) return;
    float vx = ev[3*e+0], vy = ev[3*e+1], vz = ev[3*e+2];
    float dist = sqrtf(vx*vx + vy*vy + vz*vz);
    float nx0 = vx/dist, nx1 = vy/dist, nx2 = vz/dist;

    float r0 = er[3*e+0]-0.5f, r1 = er[3*e+1]-0.5f, r2 = er[3*e+2]-0.5f;
    float rn = sqrtf(r0*r0 + r1*r1 + r2*r2);
    float a0 = r0/rn, a1 = r1/rn, a2 = r2/rn;
    float b0 = -a1, b1 = a0, b2 = a2;
    float c0 = a0, c1 = -a2, c2 = a1;

    float da = fabsf(a0*nx0 + a1*nx1 + a2*nx2);
    float db = fabsf(b0*nx0 + b1*nx1 + b2*nx2);
    float dc = fabsf(c0*nx0 + c1*nx1 + c2*nx2);

    float e0 = a0, e1 = a1, e2c_ = a2, dcur = da;
    if (dcur > db) { e0 = b0; e1 = b1; e2c_ = b2; dcur = db; }
    if (dcur > dc) { e0 = c0; e1 = c1; e2c_ = c2; }

    float z0 = nx1*e2c_ - nx2*e1;
    float z1 = nx2*e0   - nx0*e2c_;
    float z2 = nx0*e1   - nx1*e0;
    float zn = sqrtf(z0*z0 + z1*z1 + z2*z2);
    z0 /= zn; z1 /= zn; z2 /= zn;
    float y0 = nx1*z2 - nx2*z1;
    float y1 = nx2*z0 - nx0*z2;
    float y2 = nx0*z1 - nx1*z0;
    float yn = sqrtf(y0*y0 + y1*y1 + y2*y2);
    y0 /= yn; y1 /= yn; y2 /= yn;

    float* R = rot + (size_t)e * 9;
    R[0] =  z0; R[1] =  z1; R[2] =  z2;
    R[3] = nx0; R[4] = nx1; R[5] = nx2;
    R[6] = -y0; R[7] = -y1; R[8] = -y2;
}

#define PL 132   // X/staging pitch
#define PB 136   // packed-W smem pitch

// ====================== fused QKV linear (R15-proven) ======================
template<int L>
__global__ void __launch_bounds__(256) qkv_tf32(const float* __restrict__ x,
                                                const float* __restrict__ Wqp,
                                                const float* __restrict__ Wkp,
                                                const float* __restrict__ Wvp,
                                                float* __restrict__ q,
                                                float* __restrict__ k,
                                                float* __restrict__ v)
{
    constexpr int d = 2*L + 1;
    constexpr int s = (L == 0) ? 0 : (L == 1 ? 128 : 512);
    constexpr int ntiles = (NN * d) / 64;
    constexpr int PX = 128*d + 4;
    constexpr int NMAX = 64/d + 2;
    constexpr int TC = NMAX*32*d;
    constexpr int CH = (TC + 255)/256;

    extern __shared__ float sm[];
    float* Xs = sm;
    float* Bs = sm + NMAX*PX;       // [3][32][PB]

    const int tid  = threadIdx.x;
    const int lane = tid & 31, wid = tid >> 5;
    const int gr   = lane >> 2, th = lane & 3;
    const int wr   = wid >> 1, wc = wid & 1;
    const int obase = blockIdx.y * 32;

    for (int i = tid; i < 3*32*32; i += 256) {
        int wi = i >> 10, rem = i & 1023;
        int o = rem >> 5, c4 = (rem & 31) * 4;
        const float* wp = (wi == 0) ? Wqp : (wi == 1 ? Wkp : Wvp);
        cp16(&Bs[(wi*32 + o)*PB + c4], &wp[(obase + o)*128 + c4]);
    }
    cp_commit();

    const float scale = 0.08838834764831845f;

    float4 xr[CH];
    {
        const int n0 = (blockIdx.x * 64) / d;
        #pragma unroll
        for (int u = 0; u < CH; u++) {
            int i = tid + u*256;
            if (i < TC) {
                int node = i / (32*d);
                int j = (i - node*32*d) * 4;
                int nn = n0 + node; if (nn > NN-1) nn = NN-1;
                xr[u] = *(const float4*)&x[(size_t)nn*DD + s + j];
            }
        }
    }
    cp_wait0();

    for (int t = blockIdx.x; t < ntiles; t += gridDim.x) {
        const int r0 = t * 64;
        const int n0 = r0 / d;

        __syncthreads();
        #pragma unroll
        for (int u = 0; u < CH; u++) {
            int i = tid + u*256;
            if (i < TC) {
                int node = i / (32*d);
                int j = (i - node*32*d) * 4;
                *(float4*)&Xs[node*PX + j] = xr[u];
            }
        }
        __syncthreads();

        const int t2 = t + gridDim.x;
        if (t2 < ntiles) {
            const int n02 = (t2 * 64) / d;
            #pragma unroll
            for (int u = 0; u < CH; u++) {
                int i = tid + u*256;
                if (i < TC) {
                    int node = i / (32*d);
                    int j = (i - node*32*d) * 4;
                    int nn = n02 + node; if (nn > NN-1) nn = NN-1;
                    xr[u] = *(const float4*)&x[(size_t)nn*DD + s + j];
                }
            }
        }

        const int rowA0 = r0 + wr*16 + gr;
        const int rowA1 = rowA0 + 8;
        const int nA0 = rowA0 / d, mA0 = rowA0 - nA0*d;
        const int nA1 = rowA1 / d, mA1 = rowA1 - nA1*d;
        const float* X0 = Xs + (nA0 - n0)*PX + mA0 + th*d;
        const float* X1 = Xs + (nA1 - n0)*PX + mA1 + th*d;

        float acc[3][2][4];
        #pragma unroll
        for (int wi = 0; wi < 3; wi++)
            #pragma unroll
            for (int nt = 0; nt < 2; nt++)
                #pragma unroll
                for (int j = 0; j < 4; j++) acc[wi][nt][j] = 0.f;

        #pragma unroll 4
        for (int ks = 0; ks < 16; ks++) {
            const int co = ks * 8 * d;
            uint32 a0 = __float_as_uint(X0[co      ]);
            uint32 a1 = __float_as_uint(X1[co      ]);
            uint32 a2 = __float_as_uint(X0[co + 4*d]);
            uint32 a3 = __float_as_uint(X1[co + 4*d]);
            #pragma unroll
            for (int wi = 0; wi < 3; wi++)
                #pragma unroll
                for (int nt = 0; nt < 2; nt++) {
                    float2 bp = *(const float2*)&Bs[(wi*32 + wc*16 + nt*8 + gr)*PB + ks*8 + th*2];
                    mma_tf32(acc[wi][nt], a0, a1, a2, a3,
                             __float_as_uint(bp.x), __float_as_uint(bp.y));
                }
        }

        #pragma unroll
        for (int wi = 0; wi < 3; wi++) {
            float* yp = (wi == 0) ? q : (wi == 1 ? k : v);
            #pragma unroll
            for (int r = 0; r < 2; r++) {
                int rg = r0 + wr*16 + gr + 8*r;
                int n = rg / d, m = rg - n * d;
                float* yb = yp + (size_t)n*DD + s + m;
                #pragma unroll
                for (int nt = 0; nt < 2; nt++) {
                    int o = obase + wc*16 + nt*8 + 2*th;
                    yb[(o  )*d] = acc[wi][nt][2*r  ] * scale;
                    yb[(o+1)*d] = acc[wi][nt][2*r+1] * scale;
                }
            }
        }
    }
}

// ====================== W_o l=0 + residual + LN + SiLU fused (packed-B) ======================
// d=1: tile = 64 nodes, all 128 output channels in-CTA. Writes out[:, 0:128].
__global__ void __launch_bounds__(256) wo0_fused(const float* __restrict__ xin,
                                                 const float* __restrict__ Wp,
                                                 const float* __restrict__ xnf,
                                                 const float* __restrict__ gamma,
                                                 const float* __restrict__ beta,
                                                 float* __restrict__ out)
{
    extern __shared__ float sm[];
    float* Xs = sm;             // [64][132]; reused as staging [64][132]
    float* Bs = sm + 64*PL;     // [128][PB]

    const int tid  = threadIdx.x;
    const int lane = tid & 31, wid = tid >> 5;
    const int gr   = lane >> 2, th = lane & 3;
    const int wr   = wid >> 1, wc = wid & 1;
    const int warpRow = wr * 16;
    const int colBase = wc * 64;
    const int r0   = blockIdx.x * 64;

    for (int i = tid; i < 4096; i += 256) {
        int o = i >> 5, c4 = (i & 31) * 4;
        cp16(&Bs[o*PB + c4], &Wp[o*128 + c4]);
    }
    for (int i = tid; i < 64*32; i += 256) {
        int row = i >> 5, j = (i & 31) * 4;
        cp16(&Xs[row*PL + j], &xin[(size_t)(r0+row)*DD + j]);
    }
    cp_commit();
    cp_wait0();
    __syncthreads();

    float acc[8][4];
    #pragma unroll
    for (int nt = 0; nt < 8; nt++)
        #pragma unroll
        for (int j = 0; j < 4; j++) acc[nt][j] = 0.f;

    const float* X0 = Xs + (warpRow + gr    )*PL + th;
    const float* X1 = Xs + (warpRow + gr + 8)*PL + th;

    #pragma unroll 4
    for (int ks = 0; ks < 16; ks++) {
        const int co = ks * 8;
        uint32 a0 = __float_as_uint(X0[co    ]);
        uint32 a1 = __float_as_uint(X1[co    ]);
        uint32 a2 = __float_as_uint(X0[co + 4]);
        uint32 a3 = __float_as_uint(X1[co + 4]);
        #pragma unroll
        for (int nt = 0; nt < 8; nt++) {
            float2 bp = *(const float2*)&Bs[(colBase + nt*8 + gr)*PB + ks*8 + th*2];
            mma_tf32(acc[nt], a0, a1, a2, a3,
                     __float_as_uint(bp.x), __float_as_uint(bp.y));
        }
    }

    __syncthreads();   // Xs reads done -> reuse as staging
    const float scale = 0.08838834764831845f;
    float* Ss = Xs;    // [64][PL], 132%4==0 -> aligned LDS.128
    #pragma unroll
    for (int r = 0; r < 2; r++) {
        int row = warpRow + gr + 8*r;
        #pragma unroll
        for (int nt = 0; nt < 8; nt++) {
            int o = colBase + nt*8 + 2*th;
            *(float2*)&Ss[row*PL + o] =
                make_float2(acc[nt][2*r]*scale, acc[nt][2*r+1]*scale);
        }
    }
    __syncthreads();

    // LN pass: 4 threads per row, 32 channels each
    {
        const int row = tid >> 2, sub = tid & 3;
        const int n = r0 + row;
        const int c0 = sub * 32;
        float val[32];
        float s1 = 0.f, s2 = 0.f;
        #pragma unroll
        for (int u = 0; u < 8; u++) {
            float4 a = *(const float4*)&Ss[row*PL + c0 + u*4];
            float4 b = *(const float4*)&xnf[(size_t)n*DD + c0 + u*4];
            val[u*4+0] = a.x + b.x; val[u*4+1] = a.y + b.y;
            val[u*4+2] = a.z + b.z; val[u*4+3] = a.w + b.w;
            s1 += val[u*4+0]+val[u*4+1]+val[u*4+2]+val[u*4+3];
            s2 += val[u*4+0]*val[u*4+0]+val[u*4+1]*val[u*4+1]
                + val[u*4+2]*val[u*4+2]+val[u*4+3]*val[u*4+3];
        }
        s1 += __shfl_xor_sync(0xffffffffu, s1, 1);
        s1 += __shfl_xor_sync(0xffffffffu, s1, 2);
        s2 += __shfl_xor_sync(0xffffffffu, s2, 1);
        s2 += __shfl_xor_sync(0xffffffffu, s2, 2);
        float mu = s1 * (1.f/128.f);
        float var = s2 * (1.f/128.f) - mu*mu;
        float rv = rsqrtf(var + 1e-5f);
        #pragma unroll
        for (int u = 0; u < 8; u++) {
            float4 g4 = *(const float4*)&gamma[c0 + u*4];
            float4 b4 = *(const float4*)&beta[c0 + u*4];
            float4 o4;
            float z;
            z = (val[u*4+0]-mu)*rv*g4.x + b4.x; o4.x = z / (1.f + __expf(-z));
            z = (val[u*4+1]-mu)*rv*g4.y + b4.y; o4.y = z / (1.f + __expf(-z));
            z = (val[u*4+2]-mu)*rv*g4.z + b4.z; o4.z = z / (1.f + __expf(-z));
            z = (val[u*4+3]-mu)*rv*g4.w + b4.w; o4.w = z / (1.f + __expf(-z));
            *(float4*)&out[(size_t)n*DD + c0 + u*4] = o4;
        }
    }
}

// ====================== W_o l=1/2 + residual, writes out directly (packed-B) ======================
template<int L>
__global__ void __launch_bounds__(256) wo_tf32(const float* __restrict__ x,
                                               const float* __restrict__ Wp,
                                               const float* __restrict__ xnf,
                                               float* __restrict__ y)
{
    constexpr int d = 2*L + 1;
    constexpr int s = (L == 0) ? 0 : (L == 1 ? 128 : 512);
    constexpr int ntiles = (NN * d) / 64;
    constexpr int PX = 128*d + 4;
    constexpr int NMAX = 64/d + 2;
    constexpr int TC = NMAX*32*d;
    constexpr int CH = (TC + 255)/256;

    extern __shared__ float sm[];
    float* Xs = sm;
    float* Bs = sm + NMAX*PX;       // [128][PB]

    const int tid  = threadIdx.x;
    const int lane = tid & 31, wid = tid >> 5;
    const int gr   = lane >> 2, th = lane & 3;
    const int wr   = wid >> 1, wc = wid & 1;
    const int warpRow = wr * 16;
    const int colBase = wc * 64;

    for (int i = tid; i < 4096; i += 256) {
        int o = i >> 5, c4 = (i & 31) * 4;
        cp16(&Bs[o*PB + c4], &Wp[o*128 + c4]);
    }
    cp_commit();

    const float scale = 0.08838834764831845f;

    float4 xr[CH];
    {
        const int n0 = (blockIdx.x * 64) / d;
        #pragma unroll
        for (int u = 0; u < CH; u++) {
            int i = tid + u*256;
            if (i < TC) {
                int node = i / (32*d);
                int j = (i - node*32*d) * 4;
                int nn = n0 + node; if (nn > NN-1) nn = NN-1;
                xr[u] = *(const float4*)&x[(size_t)nn*DD + s + j];
            }
        }
    }
    cp_wait0();

    for (int t = blockIdx.x; t < ntiles; t += gridDim.x) {
        const int r0 = t * 64;
        const int n0 = r0 / d;

        __syncthreads();
        #pragma unroll
        for (int u = 0; u < CH; u++) {
            int i = tid + u*256;
            if (i < TC) {
                int node = i / (32*d);
                int j = (i - node*32*d) * 4;
                *(float4*)&Xs[node*PX + j] = xr[u];
            }
        }
        __syncthreads();

        const int t2 = t + gridDim.x;
        if (t2 < ntiles) {
            const int n02 = (t2 * 64) / d;
            #pragma unroll
            for (int u = 0; u < CH; u++) {
                int i = tid + u*256;
                if (i < TC) {
                    int node = i / (32*d);
                    int j = (i - node*32*d) * 4;
                    int nn = n02 + node; if (nn > NN-1) nn = NN-1;
                    xr[u] = *(const float4*)&x[(size_t)nn*DD + s + j];
                }
            }
        }

        const int rowA0 = r0 + warpRow + gr;
        const int rowA1 = rowA0 + 8;
        const int nA0 = rowA0 / d, mA0 = rowA0 - nA0*d;
        const int nA1 = rowA1 / d, mA1 = rowA1 - nA1*d;
        const float* X0 = Xs + (nA0 - n0)*PX + mA0 + th*d;
        const float* X1 = Xs + (nA1 - n0)*PX + mA1 + th*d;

        float acc[8][4];
        #pragma unroll
        for (int nt = 0; nt < 8; nt++)
            #pragma unroll
            for (int j = 0; j < 4; j++) acc[nt][j] = 0.f;

        #pragma unroll 4
        for (int ks = 0; ks < 16; ks++) {
            const int co = ks * 8 * d;
            uint32 a0 = __float_as_uint(X0[co      ]);
            uint32 a1 = __float_as_uint(X1[co      ]);
            uint32 a2 = __float_as_uint(X0[co + 4*d]);
            uint32 a3 = __float_as_uint(X1[co + 4*d]);
            #pragma unroll
            for (int nt = 0; nt < 8; nt++) {
                float2 bp = *(const float2*)&Bs[(colBase + nt*8 + gr)*PB + ks*8 + th*2];
                mma_tf32(acc[nt], a0, a1, a2, a3,
                         __float_as_uint(bp.x), __float_as_uint(bp.y));
            }
        }

        #pragma unroll
        for (int r = 0; r < 2; r++) {
            int rg = r0 + warpRow + gr + 8*r;
            int n = rg / d, m = rg - n * d;
            float* yb = y + (size_t)n*DD + s + m;
            const float* xb = xnf + (size_t)n*DD + s + m;
            #pragma unroll
            for (int nt = 0; nt < 8; nt++) {
                int o = colBase + nt*8 + 2*th;
                yb[(o  )*d] = xb[(o  )*d] + acc[nt][2*r  ] * scale;
                yb[(o+1)*d] = xb[(o+1)*d] + acc[nt][2*r+1] * scale;
            }
        }
    }
}

// ====================== flash attention (R10-proven, non-pipelined) ======================
#define PQ 148
#define PVP 152
#define PP 52

__global__ void __launch_bounds__(128) attn_kernel(const float* __restrict__ q,
                                                   const float* __restrict__ k,
                                                   const float* __restrict__ v,
                                                   float* __restrict__ o)
{
    extern __shared__ float sm[];
    float* Qs = sm;               // [64][148]
    float* Ks = Qs + 64*PQ;       // [32][148]
    float* Vs = Ks + 32*PQ;       // [32][152]
    float* Ps = Vs + 32*PVP;      // [64][52]

    const int tid  = threadIdx.x;
    const int wid  = tid >> 5, lane = tid & 31;
    const int gr   = lane >> 2, th = lane & 3;
    const int b    = blockIdx.y >> 3, h = blockIdx.y & 7;
    const int q0   = blockIdx.x * 64;
    const size_t hoff  = (size_t)h * 144;
    const size_t bbase = (size_t)b * 512;
    const float qscale = 1.0f / 12.0f;

    for (int f = tid; f < 64*36; f += 128) {
        int row = f / 36, cs = (f % 36) * 4;
        cp16(&Qs[row*PQ + cs], &q[(bbase + q0 + row) * DD + hoff + cs]);
    }
    cp_commit();

    float m_i[2] = {-1e30f, -1e30f};
    float l_i[2] = {0.f, 0.f};
    float oac[18][4];
    #pragma unroll
    for (int nt = 0; nt < 18; nt++)
        #pragma unroll
        for (int j = 0; j < 4; j++) oac[nt][j] = 0.f;

    const int warpRow = 16 * wid;

    for (int kt = 0; kt < 512; kt += 32) {
        __syncthreads();
        for (int f = tid; f < 32*36; f += 128) {
            int row = f / 36, cs = (f % 36) * 4;
            size_t g = (bbase + kt + row) * (size_t)DD + hoff + cs;
            cp16(&Ks[row*PQ  + cs], &k[g]);
            cp16(&Vs[row*PVP + cs], &v[g]);
        }
        cp_commit();
        cp_wait0();
        __syncthreads();

        float s_[4][4];
        #pragma unroll
        for (int nt = 0; nt < 4; nt++)
            #pragma unroll
            for (int j = 0; j < 4; j++) s_[nt][j] = 0.f;

        #pragma unroll 3
        for (int ks = 0; ks < 18; ks++) {
            int k0 = ks * 8;
            const float* Qr = Qs + k0 + th;
            uint32 a0 = __float_as_uint(Qr[(warpRow + gr    ) * PQ    ]);
            uint32 a1 = __float_as_uint(Qr[(warpRow + gr + 8) * PQ    ]);
            uint32 a2 = __float_as_uint(Qr[(warpRow + gr    ) * PQ + 4]);
            uint32 a3 = __float_as_uint(Qr[(warpRow + gr + 8) * PQ + 4]);
            #pragma unroll
            for (int nt = 0; nt < 4; nt++) {
                const float* Kr = Ks + (nt*8 + gr) * PQ + k0 + th;
                uint32 b0 = __float_as_uint(Kr[0]);
                uint32 b1 = __float_as_uint(Kr[4]);
                mma_tf32(s_[nt], a0, a1, a2, a3, b0, b1);
            }
        }

        #pragma unroll
        for (int nt = 0; nt < 4; nt++)
            #pragma unroll
            for (int j = 0; j < 4; j++) s_[nt][j] *= qscale;

        #pragma unroll
        for (int r = 0; r < 2; r++) {
            float rm = -1e30f;
            #pragma unroll
            for (int nt = 0; nt < 4; nt++)
                rm = fmaxf(rm, fmaxf(s_[nt][2*r], s_[nt][2*r+1]));
            rm = fmaxf(rm, __shfl_xor_sync(0xffffffffu, rm, 1));
            rm = fmaxf(rm, __shfl_xor_sync(0xffffffffu, rm, 2));
            float newm = fmaxf(m_i[r], rm);
            float rs = 0.f;
            #pragma unroll
            for (int nt = 0; nt < 4; nt++) {
                float p0 = __expf(s_[nt][2*r  ] - newm);
                float p1 = __expf(s_[nt][2*r+1] - newm);
                s_[nt][2*r] = p0; s_[nt][2*r+1] = p1;
                rs += p0 + p1;
            }
            rs += __shfl_xor_sync(0xffffffffu, rs, 1);
            rs += __shfl_xor_sync(0xffffffffu, rs, 2);
            float corr = __expf(m_i[r] - newm);
            l_i[r] = l_i[r] * corr + rs;
            m_i[r] = newm;
            #pragma unroll
            for (int nt = 0; nt < 18; nt++) {
                oac[nt][2*r  ] *= corr;
                oac[nt][2*r+1] *= corr;
            }
        }

        #pragma unroll
        for (int nt = 0; nt < 4; nt++) {
            int col = nt*8 + 2*th;
            Ps[(warpRow + gr    ) * PP + col    ] = s_[nt][0];
            Ps[(warpRow + gr    ) * PP + col + 1] = s_[nt][1];
            Ps[(warpRow + gr + 8) * PP + col    ] = s_[nt][2];
            Ps[(warpRow + gr + 8) * PP + col + 1] = s_[nt][3];
        }
        __syncwarp();

        #pragma unroll
        for (int ks = 0; ks < 4; ks++) {
            int k0 = ks * 8;
            const float* Pr = Ps + k0 + th;
            uint32 a0 = __float_as_uint(Pr[(warpRow + gr    ) * PP    ]);
            uint32 a1 = __float_as_uint(Pr[(warpRow + gr + 8) * PP    ]);
            uint32 a2 = __float_as_uint(Pr[(warpRow + gr    ) * PP + 4]);
            uint32 a3 = __float_as_uint(Pr[(warpRow + gr + 8) * PP + 4]);
            const float* Vb = Vs + (k0 + th) * PVP + gr;
            #pragma unroll
            for (int nt = 0; nt < 18; nt++) {
                uint32 b0 = __float_as_uint(Vb[nt*8]);
                uint32 b1 = __float_as_uint(Vb[nt*8 + 4*PVP]);
                mma_tf32(oac[nt], a0, a1, a2, a3, b0, b1);
            }
        }
    }

    #pragma unroll
    for (int r = 0; r < 2; r++) {
        float inv = 1.0f / l_i[r];
        int row = q0 + warpRow + gr + 8*r;
        float* ob = o + (bbase + row) * (size_t)DD + hoff;
        #pragma unroll
        for (int nt = 0; nt < 18; nt++) {
            int col = nt*8 + 2*th;
            ob[col    ] = oac[nt][2*r  ] * inv;
            ob[col + 1] = oac[nt][2*r+1] * inv;
        }
    }
}

// ====================== launch ======================
extern "C" void kernel_launch(void* const* d_in, const int* in_sizes, int n_in,
                              void* d_out, int out_size)
{
    const float* x     = (const float*)d_in[0];
    const float* ev    = (const float*)d_in[1];
    const float* er    = (const float*)d_in[2];
    const float* Wq    = (const float*)d_in[3];
    const float* Wk    = (const float*)d_in[4];
    const float* Wv    = (const float*)d_in[5];
    const float* Wo    = (const float*)d_in[6];
    const float* gamma = (const float*)d_in[7];
    const float* beta  = (const float*)d_in[8];
    float* out  = (float*)d_out;
    float* rotp = out + (size_t)NN * DD;

    float *qp, *kp, *vp, *op, *wp;
    cudaGetSymbolAddress((void**)&qp, g_q);
    cudaGetSymbolAddress((void**)&kp, g_k);
    cudaGetSymbolAddress((void**)&vp, g_v);
    cudaGetSymbolAddress((void**)&op, g_o);
    cudaGetSymbolAddress((void**)&wp, g_wp);

    const int SMF0 = (66*132 + 96*PB) * 4;   // 87072
    const int SMF1 = (23*388 + 96*PB) * 4;   // 87920
    const int SMF2 = (14*644 + 96*PB) * 4;   // 88288
    const int SMWF = (64*PL + 128*PB) * 4;   // 103424 (wo0_fused)
    const int SMW1 = (23*388 + 128*PB) * 4;  // 105328
    const int SMW2 = (14*644 + 128*PB) * 4;  // 105696
    const int SMA  = (64*PQ + 32*PQ + 32*PVP + 64*PP) * 4;  // 89600

    cudaFuncSetAttribute((const void*)qkv_tf32<0>, cudaFuncAttributeMaxDynamicSharedMemorySize, SMF0);
    cudaFuncSetAttribute((const void*)qkv_tf32<1>, cudaFuncAttributeMaxDynamicSharedMemorySize, SMF1);
    cudaFuncSetAttribute((const void*)qkv_tf32<2>, cudaFuncAttributeMaxDynamicSharedMemorySize, SMF2);
    cudaFuncSetAttribute((const void*)wo0_fused,   cudaFuncAttributeMaxDynamicSharedMemorySize, SMWF);
    cudaFuncSetAttribute((const void*)wo_tf32<1>,  cudaFuncAttributeMaxDynamicSharedMemorySize, SMW1);
    cudaFuncSetAttribute((const void*)wo_tf32<2>,  cudaFuncAttributeMaxDynamicSharedMemorySize, SMW2);
    cudaFuncSetAttribute((const void*)attn_kernel, cudaFuncAttributeMaxDynamicSharedMemorySize, SMA);

    pack_w_kernel<<<768, 256>>>(Wq, Wk, Wv, Wo, wp);
    rot_kernel<<<EE/256, 256>>>(ev, er, rotp);

    // packed weight bases: wp + w*49152 + L*16384
    qkv_tf32<0><<<dim3(32, 4), 256, SMF0>>>(x, wp,           wp + 49152,           wp + 2*49152,           qp, kp, vp);
    qkv_tf32<1><<<dim3(96, 4), 256, SMF1>>>(x, wp + 16384,   wp + 49152 + 16384,   wp + 2*49152 + 16384,   qp, kp, vp);
    qkv_tf32<2><<<dim3(80, 4), 256, SMF2>>>(x, wp + 32768,   wp + 49152 + 32768,   wp + 2*49152 + 32768,   qp, kp, vp);

    attn_kernel<<<dim3(8, 128), 128, SMA>>>(qp, kp, vp, op);

    // W_o + residual (+ LN/SiLU for l=0) fused, writing out directly
    wo0_fused<<<128, 256, SMWF>>>(op, wp + 3*49152, x, gamma, beta, out);
    wo_tf32<1><<<384, 256, SMW1>>>(op, wp + 3*49152 + 16384, x, out);
    wo_tf32<2><<<320, 256, SMW2>>>(op, wp + 3*49152 + 32768, x, out);
}